// round 7
// baseline (speedup 1.0000x reference)
#include <cuda_runtime.h>

// ---- problem constants (L=512 fixed; B,T derived from sizes) ----
#define LFIX   512
#define TILE   64
#define NT     8
#define NPAIR  36            // NT*(NT+1)/2
#define MAXB   16
#define SCONST 2.1972245773362196f   // log(9)

// double-buffered rowsum partials: [buf][b][tile][contrib][row]
__device__ float g_part[(size_t)2 * MAXB * NT * NT * TILE];
__device__ int   g_cnt [MAXB * NT];    // per (batch,tile) monotonic release counters

__device__ __forceinline__ float sigmoidf_(float v) { return 1.f / (1.f + __expf(-v)); }

// smem (floats): sW 4096 | sM 4096 | sA 4096 | sPC 1024 | sC 128
#define SMEM_FLOATS (4096 * 3 + 1024 + 128)

__device__ __forceinline__ void decode_pair(int p, int &ti, int &tj) {
    int t = 0;
    while (p >= NT - t) { p -= NT - t; t++; }
    ti = t; tj = t + p;
}

__device__ __forceinline__ size_t part_idx(int buf, int b, int tile, int contrib) {
    return ((((size_t)buf * MAXB + b) * NT + tile) * NT + contrib) * TILE;
}

__global__ void __launch_bounds__(256, 4) persist_kernel(
    float* __restrict__ out, const float* __restrict__ uin,
    const float* __restrict__ xin, int B, int T)
{
    extern __shared__ float sm[];
    float* sW  = sm;              // w tile, i-major swizzled
    float* sM  = sW + 4096;       // m tile, i-major swizzled
    float* sA  = sM + 4096;       // s staging, i-major swizzled
    float* sPC = sA + 4096;       // col-sum partials [tyy][j] (16 x 64)
    float* sC  = sPC + 1024;      // c_i (0..63), c_j (64..127)

    const int job = blockIdx.x;
    const int b = job / NPAIR;
    int p = job % NPAIR;
    int ti, tj; decode_pair(p, ti, tj);
    const bool diag = (ti == tj);
    const int tid = threadIdx.x;
    const int tx = tid & 15, tyy = tid >> 4;
    const int i0 = 4 * tyy, j0 = 4 * tx;
    const int L = LFIX;
    const size_t usz   = (size_t)B * L * L;
    const size_t mbase = (size_t)b * L * L;
    const int swzg = 4 * (tx ^ (tyy & 7));

    const float* uA = uin + mbase + (size_t)(ti * TILE) * L + tj * TILE;
    const float* uB = uin + mbase + (size_t)(tj * TILE) * L + ti * TILE;

    float ah1[16], ah2[16];   // a_hat(i,j) / a_hat(j,i), persistent in registers
    float lam = 0.f;

    // ================= init: u_mod, a_hat0, w, m, s0 =================
    {
        float4 u2v[4], xj[4];
        #pragma unroll
        for (int jj = 0; jj < 4; jj++) {
            u2v[jj] = *(const float4*)&uB[(size_t)(j0 + jj) * L + i0];
            xj[jj]  = *(const float4*)&xin[(size_t)(b * L + tj * TILE + j0 + jj) * 4];
        }
        float cs4[4] = {0.f, 0.f, 0.f, 0.f};
        #pragma unroll
        for (int ii = 0; ii < 4; ii++) {
            const int i = i0 + ii, gi = ti * TILE + i;
            float4 u1v = *(const float4*)&uA[(size_t)i * L + j0];
            float4 xi  = *(const float4*)&xin[(size_t)(b * L + ti * TILE + i) * 4];
            float w4[4], m4[4], s4[4];
            #pragma unroll
            for (int jj = 0; jj < 4; jj++) {
                const int gj = tj * TILE + j0 + jj;
                float u1 = ((const float*)&u1v)[jj];
                float u2 = ((const float*)&u2v[jj])[ii];
                float um1 = sigmoidf_(2.f * (u1 - SCONST)) * u1;
                float um2 = sigmoidf_(2.f * (u2 - SCONST)) * u2;
                float a1 = sigmoidf_(um1) * sigmoidf_(2.f * (um1 - SCONST));
                float a2 = sigmoidf_(um2) * sigmoidf_(2.f * (um2 - SCONST));
                ah1[ii * 4 + jj] = a1;
                ah2[ii * 4 + jj] = a2;
                w4[jj] = 0.5f * (um1 + um2);
                int d = gi - gj; if (d < 0) d = -d;
                float m = 0.f;
                if (d > 3) {
                    float A2 = ((const float*)&xj[jj])[0], U2 = ((const float*)&xj[jj])[1];
                    float C2 = ((const float*)&xj[jj])[2], G2 = ((const float*)&xj[jj])[3];
                    m = xi.x * U2 + xi.y * A2 + xi.z * G2 + xi.w * C2 + xi.y * G2 + xi.w * U2;
                }
                m4[jj] = m;
                float s = 0.5f * m * (a1 * a1 + a2 * a2);
                s4[jj] = s;
                cs4[jj] += s;
            }
            *(float4*)&sW[i * 64 + swzg] = make_float4(w4[0], w4[1], w4[2], w4[3]);
            *(float4*)&sM[i * 64 + swzg] = make_float4(m4[0], m4[1], m4[2], m4[3]);
            *(float4*)&sA[i * 64 + swzg] = make_float4(s4[0], s4[1], s4[2], s4[3]);
        }
        if (!diag)
            *(float4*)&sPC[tyy * 64 + j0] = make_float4(cs4[0], cs4[1], cs4[2], cs4[3]);
        __syncthreads();

        // partial rowsums -> g_part (round 0, buffer 0)
        if (tid < 64) {
            float4 acc = make_float4(0.f, 0.f, 0.f, 0.f);
            #pragma unroll
            for (int g = 0; g < 16; g++) {
                int gg = (g + tid) & 15;
                float4 v = *(const float4*)&sA[tid * 64 + 4 * gg];
                acc.x += v.x; acc.y += v.y; acc.z += v.z; acc.w += v.w;
            }
            g_part[part_idx(0, b, ti, tj) + tid] = acc.x + acc.y + acc.z + acc.w;
        } else if (tid < 128 && !diag) {
            int j = tid - 64;
            float a0 = 0.f, a1_ = 0.f, a2_ = 0.f, a3_ = 0.f;
            #pragma unroll
            for (int q = 0; q < 16; q += 4) {
                a0 += sPC[(q + 0) * 64 + j];
                a1_ += sPC[(q + 1) * 64 + j];
                a2_ += sPC[(q + 2) * 64 + j];
                a3_ += sPC[(q + 3) * 64 + j];
            }
            g_part[part_idx(0, b, tj, ti) + j] = a0 + a1_ + a2_ + a3_;
        }
        __threadfence();
        __syncthreads();
        if (tid == 0) {
            atomicAdd(&g_cnt[b * NT + ti], 1);
            if (!diag) atomicAdd(&g_cnt[b * NT + tj], 1);
        }
    }

    // ================= T optimization steps =================
    float alpha = 0.01f, beta_run = 0.1f;
    for (int t = 0; t < T; t++) {
        const float tau = alpha * 0.99f;    // RHO * alpha * DECAY

        // ---- wait for round-t partials of tiles ti, tj ----
        if (tid == 0) {
            const int tgt = 8 * (t + 1);
            volatile int* c1 = &g_cnt[b * NT + ti];
            volatile int* c2 = &g_cnt[b * NT + tj];
            while (*c1 < tgt) __nanosleep(16);
            while (*c2 < tgt) __nanosleep(16);
            __threadfence();
        }
        __syncthreads();

        // ---- reconstruct rs_t, lambda_t, c_t for this block's rows ----
        if (tid < 128) {
            const int tile = (tid < 64) ? ti : tj;
            const int row  = (tid < 64) ? tid : (tid - 64);
            const float* pp = g_part + part_idx(t & 1, b, tile, 0) + row;
            float rst = 0.f;
            #pragma unroll
            for (int s = 0; s < 8; s++) rst += __ldcg(&pp[(size_t)s * TILE]);
            float rl = fmaxf(rst - 1.f, 0.f);
            lam = (t == 0) ? rl : (lam + beta_run * rl);
            sC[tid] = lam * sigmoidf_(2.f * (rst - 1.f));
        }
        __syncthreads();

        float4 ci4 = *(const float4*)&sC[i0];
        float4 cj4 = *(const float4*)&sC[64 + j0];
        float cs4[4] = {0.f, 0.f, 0.f, 0.f};
        float* outT = out + (size_t)t * usz + mbase;

        #pragma unroll
        for (int ii = 0; ii < 4; ii++) {
            const int i = i0 + ii;
            float4 w4 = *(const float4*)&sW[i * 64 + swzg];
            float4 m4 = *(const float4*)&sM[i * 64 + swzg];
            const float ci = ((const float*)&ci4)[ii];
            float s4[4];
            #pragma unroll
            for (int jj = 0; jj < 4; jj++) {
                float m = ((const float*)&m4)[jj];
                float w = ((const float*)&w4)[jj];
                float coef = alpha * m * (ci + ((const float*)&cj4)[jj] - w);
                float f = 1.f - coef;
                float n1 = fminf(fmaxf(fabsf(ah1[ii * 4 + jj] * f) - tau, 0.f), 1.f);
                float n2 = fminf(fmaxf(fabsf(ah2[ii * 4 + jj] * f) - tau, 0.f), 1.f);
                ah1[ii * 4 + jj] = n1;
                ah2[ii * 4 + jj] = n2;
                float s = 0.5f * m * (n1 * n1 + n2 * n2);
                s4[jj] = s;
                cs4[jj] += s;
            }
            float4 sv = make_float4(s4[0], s4[1], s4[2], s4[3]);
            *(float4*)&sA[i * 64 + swzg] = sv;
            __stcs((float4*)&outT[(size_t)(ti * TILE + i) * L + tj * TILE + j0], sv);
        }
        if (!diag)
            *(float4*)&sPC[tyy * 64 + j0] = make_float4(cs4[0], cs4[1], cs4[2], cs4[3]);
        __syncthreads();

        // ---- rowsum partials for round t+1 + early release ----
        if (t + 1 < T) {
            const int buf = (t + 1) & 1;
            if (tid < 64) {
                float4 acc = make_float4(0.f, 0.f, 0.f, 0.f);
                #pragma unroll
                for (int g = 0; g < 16; g++) {
                    int gg = (g + tid) & 15;
                    float4 v = *(const float4*)&sA[tid * 64 + 4 * gg];
                    acc.x += v.x; acc.y += v.y; acc.z += v.z; acc.w += v.w;
                }
                g_part[part_idx(buf, b, ti, tj) + tid] = acc.x + acc.y + acc.z + acc.w;
            } else if (tid < 128 && !diag) {
                int j = tid - 64;
                float a0 = 0.f, a1_ = 0.f, a2_ = 0.f, a3_ = 0.f;
                #pragma unroll
                for (int q = 0; q < 16; q += 4) {
                    a0 += sPC[(q + 0) * 64 + j];
                    a1_ += sPC[(q + 1) * 64 + j];
                    a2_ += sPC[(q + 2) * 64 + j];
                    a3_ += sPC[(q + 3) * 64 + j];
                }
                g_part[part_idx(buf, b, tj, ti) + j] = a0 + a1_ + a2_ + a3_;
            }
            __threadfence();
            __syncthreads();
            if (tid == 0) {
                atomicAdd(&g_cnt[b * NT + ti], 1);
                if (!diag) atomicAdd(&g_cnt[b * NT + tj], 1);
            }
        }

        // ---- B (transposed) tile store AFTER release (off critical path) ----
        if (!diag) {
            #pragma unroll
            for (int jj = 0; jj < 4; jj++) {
                const int j = 4 * tyy + jj;
                const int goff = 4 * (tyy ^ (tx & 7)) + jj;
                float4 v;
                v.x = sA[(4 * tx + 0) * 64 + goff];
                v.y = sA[(4 * tx + 1) * 64 + goff];
                v.z = sA[(4 * tx + 2) * 64 + goff];
                v.w = sA[(4 * tx + 3) * 64 + goff];
                __stcs((float4*)&outT[(size_t)(tj * TILE + j) * L + ti * TILE + 4 * tx], v);
            }
        }

        if (t > 0) beta_run *= 0.99f;
        alpha *= 0.99f;
    }
}

// ---------------- host ----------------
extern "C" void kernel_launch(void* const* d_in, const int* in_sizes, int n_in,
                              void* d_out, int out_size)
{
    // identify inputs by size: u = largest, x = next largest
    int iu = 0;
    for (int i = 1; i < n_in; i++) if (in_sizes[i] > in_sizes[iu]) iu = i;
    int ix = -1;
    for (int i = 0; i < n_in; i++) {
        if (i == iu) continue;
        if (ix < 0 || in_sizes[i] > in_sizes[ix]) ix = i;
    }
    const float* u = (const float*)d_in[iu];
    const float* x = (const float*)d_in[ix];
    const long long usz = in_sizes[iu];
    const long long xsz = in_sizes[ix];
    const int L = (int)(4LL * usz / xsz);           // 512
    const int B = (int)(xsz / (4LL * L));           // 16
    const int T = (int)((long long)out_size / usz); // 20
    float* out = (float*)d_out;

    void* cnt_ptr = nullptr; cudaGetSymbolAddress(&cnt_ptr, g_cnt);
    cudaMemsetAsync(cnt_ptr, 0, sizeof(int) * MAXB * NT);

    const int smem_bytes = SMEM_FLOATS * sizeof(float);
    cudaFuncSetAttribute(persist_kernel, cudaFuncAttributeMaxDynamicSharedMemorySize, smem_bytes);

    persist_kernel<<<B * NPAIR, 256, smem_bytes>>>(out, u, x, B, T);
}

// round 8
// speedup vs baseline: 1.4125x; 1.4125x over previous
#include <cuda_runtime.h>

// ---- problem constants (L=512 fixed; B,T derived from sizes) ----
#define LFIX   512
#define TILE   64
#define NT     8
#define NPAIR  36            // NT*(NT+1)/2
#define MAXB   16
#define MAXT   32
#define SCONST 2.1972245773362196f   // log(9)

__device__ float g_rs [(size_t)(MAXT + 1) * MAXB * LFIX]; // per-step rowsums (atomic-accumulated)
__device__ int   g_bar[MAXB];                             // per-batch monotonic barrier counters

__device__ __forceinline__ float sigmoidf_(float v) { return 1.f / (1.f + __expf(-v)); }

// smem (floats): sW 4096 | sM 4096 | sA 4096 | sPC 1024 | sC 128
#define SMEM_FLOATS (4096 * 3 + 1024 + 128)

__device__ __forceinline__ void decode_pair(int p, int &ti, int &tj) {
    int t = 0;
    while (p >= NT - t) { p -= NT - t; t++; }
    ti = t; tj = t + p;
}

// arrive: CTA-scope release at bar.sync, then gpu fence + RED by one thread
__device__ __forceinline__ void batch_arrive(int b) {
    __syncthreads();
    if (threadIdx.x == 0) {
        __threadfence();
        atomicAdd(&g_bar[b], 1);
    }
}
__device__ __forceinline__ void batch_wait(int b, int target) {
    if (threadIdx.x == 0) {
        volatile int* c = g_bar + b;
        while (*c < target) __nanosleep(32);
        __threadfence();
    }
    __syncthreads();
}

__global__ void __launch_bounds__(256, 4) persist_kernel(
    float* __restrict__ out, const float* __restrict__ uin,
    const float* __restrict__ xin, int B, int T)
{
    extern __shared__ float sm[];
    float* sW  = sm;              // w tile, i-major swizzled
    float* sM  = sW + 4096;       // m tile, i-major swizzled
    float* sA  = sM + 4096;       // s staging, i-major swizzled
    float* sPC = sA + 4096;       // col-sum partials [tyy][j] (16 x 64)
    float* sC  = sPC + 1024;      // c_i (0..63), c_j (64..127)

    const int job = blockIdx.x;
    const int b = job / NPAIR;
    int p = job % NPAIR;
    int ti, tj; decode_pair(p, ti, tj);
    const bool diag = (ti == tj);
    const int tid = threadIdx.x;
    const int tx = tid & 15, tyy = tid >> 4;
    const int i0 = 4 * tyy, j0 = 4 * tx;
    const int L = LFIX;
    const size_t usz   = (size_t)B * L * L;
    const size_t mbase = (size_t)b * L * L;
    const int stride = B * L;
    const int swzg = 4 * (tx ^ (tyy & 7));

    const float* uA = uin + mbase + (size_t)(ti * TILE) * L + tj * TILE;
    const float* uB = uin + mbase + (size_t)(tj * TILE) * L + ti * TILE;

    float ah1[16], ah2[16];   // a_hat(i,j) / a_hat(j,i), persistent in registers
    float lam = 0.f;

    // ================= init: u_mod, a_hat0, w, m, s0 =================
    {
        float4 u2v[4], xj[4];
        #pragma unroll
        for (int jj = 0; jj < 4; jj++) {
            u2v[jj] = *(const float4*)&uB[(size_t)(j0 + jj) * L + i0];
            xj[jj]  = *(const float4*)&xin[(size_t)(b * L + tj * TILE + j0 + jj) * 4];
        }
        float cs4[4] = {0.f, 0.f, 0.f, 0.f};
        #pragma unroll
        for (int ii = 0; ii < 4; ii++) {
            const int i = i0 + ii, gi = ti * TILE + i;
            float4 u1v = *(const float4*)&uA[(size_t)i * L + j0];
            float4 xi  = *(const float4*)&xin[(size_t)(b * L + ti * TILE + i) * 4];
            float w4[4], m4[4], s4[4];
            #pragma unroll
            for (int jj = 0; jj < 4; jj++) {
                const int gj = tj * TILE + j0 + jj;
                float u1 = ((const float*)&u1v)[jj];
                float u2 = ((const float*)&u2v[jj])[ii];
                float um1 = sigmoidf_(2.f * (u1 - SCONST)) * u1;
                float um2 = sigmoidf_(2.f * (u2 - SCONST)) * u2;
                float a1 = sigmoidf_(um1) * sigmoidf_(2.f * (um1 - SCONST));
                float a2 = sigmoidf_(um2) * sigmoidf_(2.f * (um2 - SCONST));
                ah1[ii * 4 + jj] = a1;
                ah2[ii * 4 + jj] = a2;
                w4[jj] = 0.5f * (um1 + um2);
                int d = gi - gj; if (d < 0) d = -d;
                float m = 0.f;
                if (d > 3) {
                    float A2 = ((const float*)&xj[jj])[0], U2 = ((const float*)&xj[jj])[1];
                    float C2 = ((const float*)&xj[jj])[2], G2 = ((const float*)&xj[jj])[3];
                    m = xi.x * U2 + xi.y * A2 + xi.z * G2 + xi.w * C2 + xi.y * G2 + xi.w * U2;
                }
                m4[jj] = m;
                float s = 0.5f * m * (a1 * a1 + a2 * a2);
                s4[jj] = s;
                cs4[jj] += s;
            }
            *(float4*)&sW[i * 64 + swzg] = make_float4(w4[0], w4[1], w4[2], w4[3]);
            *(float4*)&sM[i * 64 + swzg] = make_float4(m4[0], m4[1], m4[2], m4[3]);
            *(float4*)&sA[i * 64 + swzg] = make_float4(s4[0], s4[1], s4[2], s4[3]);
        }
        if (!diag)
            *(float4*)&sPC[tyy * 64 + j0] = make_float4(cs4[0], cs4[1], cs4[2], cs4[3]);
        __syncthreads();

        // rowsum reductions -> g_rs[0]
        float* rs0 = g_rs + (size_t)b * L;
        if (tid < 64) {
            float4 acc = make_float4(0.f, 0.f, 0.f, 0.f);
            #pragma unroll
            for (int g = 0; g < 16; g++) {
                int gg = (g + tid) & 15;
                float4 v = *(const float4*)&sA[tid * 64 + 4 * gg];
                acc.x += v.x; acc.y += v.y; acc.z += v.z; acc.w += v.w;
            }
            atomicAdd(&rs0[ti * TILE + tid], acc.x + acc.y + acc.z + acc.w);
        } else if (tid < 128 && !diag) {
            int j = tid - 64;
            float a0 = 0.f, a1_ = 0.f, a2_ = 0.f, a3_ = 0.f;
            #pragma unroll
            for (int q = 0; q < 16; q += 4) {
                a0 += sPC[(q + 0) * 64 + j];
                a1_ += sPC[(q + 1) * 64 + j];
                a2_ += sPC[(q + 2) * 64 + j];
                a3_ += sPC[(q + 3) * 64 + j];
            }
            atomicAdd(&rs0[tj * TILE + j], a0 + a1_ + a2_ + a3_);
        }
        batch_arrive(b);
    }

    // ================= T optimization steps =================
    float alpha = 0.01f, beta_run = 0.1f;
    for (int t = 0; t < T; t++) {
        const float tau = alpha * 0.99f;    // RHO * alpha * DECAY

        batch_wait(b, NPAIR * (t + 1));     // round-t rowsums ready

        // ---- lambda_t, c_t for this block's 128 rows ----
        if (tid < 128) {
            int row = (tid < 64) ? (ti * TILE + tid) : (tj * TILE + (tid - 64));
            float rst = __ldcg(&g_rs[(size_t)t * stride + (size_t)b * L + row]);
            float rl = fmaxf(rst - 1.f, 0.f);
            lam = (t == 0) ? rl : (lam + beta_run * rl);
            sC[tid] = lam * sigmoidf_(2.f * (rst - 1.f));
        }
        __syncthreads();

        float4 ci4 = *(const float4*)&sC[i0];
        float4 cj4 = *(const float4*)&sC[64 + j0];
        float cs4[4] = {0.f, 0.f, 0.f, 0.f};
        float* outT = out + (size_t)t * usz + mbase;

        // ---- update + s into smem only (no global stores before the fence) ----
        #pragma unroll
        for (int ii = 0; ii < 4; ii++) {
            const int i = i0 + ii;
            float4 w4 = *(const float4*)&sW[i * 64 + swzg];
            float4 m4 = *(const float4*)&sM[i * 64 + swzg];
            const float ci = ((const float*)&ci4)[ii];
            float s4[4];
            #pragma unroll
            for (int jj = 0; jj < 4; jj++) {
                float m = ((const float*)&m4)[jj];
                float w = ((const float*)&w4)[jj];
                float coef = alpha * m * (ci + ((const float*)&cj4)[jj] - w);
                float f = 1.f - coef;
                float n1 = fminf(fmaxf(fabsf(ah1[ii * 4 + jj] * f) - tau, 0.f), 1.f);
                float n2 = fminf(fmaxf(fabsf(ah2[ii * 4 + jj] * f) - tau, 0.f), 1.f);
                ah1[ii * 4 + jj] = n1;
                ah2[ii * 4 + jj] = n2;
                float s = 0.5f * m * (n1 * n1 + n2 * n2);
                s4[jj] = s;
                cs4[jj] += s;
            }
            *(float4*)&sA[i * 64 + swzg] = make_float4(s4[0], s4[1], s4[2], s4[3]);
        }
        if (!diag)
            *(float4*)&sPC[tyy * 64 + j0] = make_float4(cs4[0], cs4[1], cs4[2], cs4[3]);
        __syncthreads();

        // ---- rowsum reductions for round t+1, then RELEASE ----
        if (t + 1 < T) {
            float* rsn = g_rs + (size_t)(t + 1) * stride + (size_t)b * L;
            if (tid < 64) {
                float4 acc = make_float4(0.f, 0.f, 0.f, 0.f);
                #pragma unroll
                for (int g = 0; g < 16; g++) {
                    int gg = (g + tid) & 15;
                    float4 v = *(const float4*)&sA[tid * 64 + 4 * gg];
                    acc.x += v.x; acc.y += v.y; acc.z += v.z; acc.w += v.w;
                }
                atomicAdd(&rsn[ti * TILE + tid], acc.x + acc.y + acc.z + acc.w);
            } else if (tid < 128 && !diag) {
                int j = tid - 64;
                float a0 = 0.f, a1_ = 0.f, a2_ = 0.f, a3_ = 0.f;
                #pragma unroll
                for (int q = 0; q < 16; q += 4) {
                    a0 += sPC[(q + 0) * 64 + j];
                    a1_ += sPC[(q + 1) * 64 + j];
                    a2_ += sPC[(q + 2) * 64 + j];
                    a3_ += sPC[(q + 3) * 64 + j];
                }
                atomicAdd(&rsn[tj * TILE + j], a0 + a1_ + a2_ + a3_);
            }
            batch_arrive(b);   // release BEFORE the bulk output stores
        }

        // ---- output stores (off the inter-block critical path) ----
        #pragma unroll
        for (int ii = 0; ii < 4; ii++) {     // A tile: read back own smem addresses
            const int i = i0 + ii;
            float4 sv = *(const float4*)&sA[i * 64 + swzg];
            __stcs((float4*)&outT[(size_t)(ti * TILE + i) * L + tj * TILE + j0], sv);
        }
        if (!diag) {                          // B (transposed) tile
            #pragma unroll
            for (int jj = 0; jj < 4; jj++) {
                const int j = 4 * tyy + jj;
                const int goff = 4 * (tyy ^ (tx & 7)) + jj;
                float4 v;
                v.x = sA[(4 * tx + 0) * 64 + goff];
                v.y = sA[(4 * tx + 1) * 64 + goff];
                v.z = sA[(4 * tx + 2) * 64 + goff];
                v.w = sA[(4 * tx + 3) * 64 + goff];
                __stcs((float4*)&outT[(size_t)(tj * TILE + j) * L + ti * TILE + 4 * tx], v);
            }
        }

        if (t > 0) beta_run *= 0.99f;
        alpha *= 0.99f;
    }
}

// ---------------- host ----------------
extern "C" void kernel_launch(void* const* d_in, const int* in_sizes, int n_in,
                              void* d_out, int out_size)
{
    // identify inputs by size: u = largest, x = next largest
    int iu = 0;
    for (int i = 1; i < n_in; i++) if (in_sizes[i] > in_sizes[iu]) iu = i;
    int ix = -1;
    for (int i = 0; i < n_in; i++) {
        if (i == iu) continue;
        if (ix < 0 || in_sizes[i] > in_sizes[ix]) ix = i;
    }
    const float* u = (const float*)d_in[iu];
    const float* x = (const float*)d_in[ix];
    const long long usz = in_sizes[iu];
    const long long xsz = in_sizes[ix];
    const int L = (int)(4LL * usz / xsz);           // 512
    const int B = (int)(xsz / (4LL * L));           // 16
    const int T = (int)((long long)out_size / usz); // 20
    float* out = (float*)d_out;

    void* rs_ptr = nullptr;  cudaGetSymbolAddress(&rs_ptr, g_rs);
    void* bar_ptr = nullptr; cudaGetSymbolAddress(&bar_ptr, g_bar);
    cudaMemsetAsync(rs_ptr, 0, sizeof(float) * (size_t)(T + 1) * B * L);
    cudaMemsetAsync(bar_ptr, 0, sizeof(int) * MAXB);

    const int smem_bytes = SMEM_FLOATS * sizeof(float);
    cudaFuncSetAttribute(persist_kernel, cudaFuncAttributeMaxDynamicSharedMemorySize, smem_bytes);

    persist_kernel<<<B * NPAIR, 256, smem_bytes>>>(out, u, x, B, T);
}